// round 16
// baseline (speedup 1.0000x reference)
#include <cuda_runtime.h>
#include <cuda_bf16.h>
#include <cstdint>

// Problem constants
#define BATCH 4
#define TSEQ  4096
#define CEMB  1024
#define HD    64
#define MTOT  (BATCH * TSEQ)          // 16384 tokens

__device__ float g_q [MTOT * HD];     // [token][d] row-major (fp32)
__device__ float g_kF[MTOT * HD];     // B-fragment-major per 64-key tile (tf32 bits)
__device__ float g_v [MTOT * HD];     // [token][d] row-major (tf32-rounded)
__device__ float g_oP[2 * MTOT * HD]; // split-K partial O (unnormalized)
__device__ float g_lP[2 * MTOT];      // split-K partial row sums
__device__ __nv_bfloat16 g_wh[3 * HD * CEMB];  // [z*64+h][c] hi
__device__ __nv_bfloat16 g_wl[3 * HD * CEMB];  // [z*64+h][c] lo

// ---- tf32 / mma helpers --------------------------------------------------
__device__ __forceinline__ uint32_t f2tf(float f) {
    uint32_t u;
    asm("cvt.rna.tf32.f32 %0, %1;" : "=r"(u) : "f"(f));
    return u;
}
__device__ __forceinline__ float tf32f(float f) { return __uint_as_float(f2tf(f)); }

__device__ __forceinline__ void mma8(float c[4], const uint32_t a[4],
                                     uint32_t b0, uint32_t b1) {
    asm volatile(
        "mma.sync.aligned.m16n8k8.row.col.f32.tf32.tf32.f32 "
        "{%0,%1,%2,%3}, {%4,%5,%6,%7}, {%8,%9}, {%0,%1,%2,%3};"
        : "+f"(c[0]), "+f"(c[1]), "+f"(c[2]), "+f"(c[3])
        : "r"(a[0]), "r"(a[1]), "r"(a[2]), "r"(a[3]), "r"(b0), "r"(b1));
}

__device__ __forceinline__ void mma16(float c[4], const uint32_t a[4],
                                      const uint32_t b[2]) {
    asm volatile(
        "mma.sync.aligned.m16n8k16.row.col.f32.bf16.bf16.f32 "
        "{%0,%1,%2,%3}, {%4,%5,%6,%7}, {%8,%9}, {%0,%1,%2,%3};"
        : "+f"(c[0]), "+f"(c[1]), "+f"(c[2]), "+f"(c[3])
        : "r"(a[0]), "r"(a[1]), "r"(a[2]), "r"(a[3]), "r"(b[0]), "r"(b[1]));
}

#define CPA16(dst_s32, src) \
    asm volatile("cp.async.ca.shared.global [%0], [%1], 16;" :: "r"(dst_s32), "l"(src))
#define CPA_COMMIT() asm volatile("cp.async.commit_group;")
#define CPA_WAIT0()  asm volatile("cp.async.wait_group 0;" ::: "memory")

__device__ __forceinline__ uint32_t packbf(__nv_bfloat16 a, __nv_bfloat16 b) {
    __nv_bfloat162 v(a, b);
    return *reinterpret_cast<uint32_t*>(&v);
}
__device__ __forceinline__ void split2(float f0, float f1,
                                       uint32_t& h, uint32_t& l) {
    __nv_bfloat16 h0 = __float2bfloat16(f0);
    __nv_bfloat16 h1 = __float2bfloat16(f1);
    __nv_bfloat16 l0 = __float2bfloat16(f0 - __bfloat162float(h0));
    __nv_bfloat16 l1 = __float2bfloat16(f1 - __bfloat162float(h1));
    h = packbf(h0, h1);
    l = packbf(l0, l1);
}

// -------------------------------------------------------------------------
// Weight split prep: w (fp32 [h][c], 3 tensors) -> g_wh/g_wl bf16 [z*64+h][c]
// -------------------------------------------------------------------------
__global__ __launch_bounds__(256) void wprep_kernel(
    const float* __restrict__ wq,
    const float* __restrict__ wk,
    const float* __restrict__ wv)
{
    const int idx  = blockIdx.x * 256 + threadIdx.x;
    const int base = idx * 4;
    const int row  = base >> 10;
    const int c    = base & 1023;
    const int z    = row >> 6;
    const int h    = row & 63;
    const float* w = (z == 0) ? wq : (z == 1) ? wk : wv;
    float4 v = *(const float4*)&w[(size_t)h * CEMB + c];
    uint32_t h01, l01, h23, l23;
    split2(v.x, v.y, h01, l01);
    split2(v.z, v.w, h23, l23);
    uint32_t* ph = (uint32_t*)&g_wh[base];
    uint32_t* pl = (uint32_t*)&g_wl[base];
    ph[0] = h01; ph[1] = h23;
    pl[0] = l01; pl[1] = l23;
}

// -------------------------------------------------------------------------
// Fused QKV projection on tensor cores (identical to R13).
// -------------------------------------------------------------------------
#define FKST 72   // smem k-stride (bf16 elems)
#define FXH 0
#define FXL (64 * FKST)
#define FWH (2 * 64 * FKST)
#define FWL (FWH + 192 * FKST)
#define FUSED_SMEM_HALFS (FWL + 192 * FKST)
#define FUSED_SMEM ((int)(FUSED_SMEM_HALFS * sizeof(__nv_bfloat16)))  // 73,728 B

__global__ __launch_bounds__(256, 2) void qkv_fused(const float* __restrict__ x)
{
    extern __shared__ __nv_bfloat16 smh[];

    const int m0   = blockIdx.x * 64;
    const int tid  = threadIdx.x;
    const int lane = tid & 31;
    const int wid  = tid >> 5;
    const int mw   = wid >> 2;    // 0..1
    const int nw   = wid & 3;     // 0..3
    const int g    = lane >> 2;
    const int t    = lane & 3;

    float c[2][6][4] = {};

    for (int k0 = 0; k0 < CEMB; k0 += 64) {
        __syncthreads();

        #pragma unroll
        for (int it = 0; it < 6; it++) {
            int ch  = tid + it * 256;
            int r   = ch >> 3;
            int c8  = (ch & 7) * 8;
            uint32_t dh = (uint32_t)__cvta_generic_to_shared(
                &smh[FWH + r * FKST + c8]);
            uint32_t dl = (uint32_t)__cvta_generic_to_shared(
                &smh[FWL + r * FKST + c8]);
            CPA16(dh, &g_wh[(size_t)r * CEMB + k0 + c8]);
            CPA16(dl, &g_wl[(size_t)r * CEMB + k0 + c8]);
        }
        CPA_COMMIT();

        #pragma unroll
        for (int it = 0; it < 4; it++) {
            int f  = tid + it * 256;
            int r  = f >> 4;
            int c4 = (f & 15) * 4;
            float4 v = *(const float4*)&x[(size_t)(m0 + r) * CEMB + k0 + c4];
            uint32_t h01, l01, h23, l23;
            split2(v.x, v.y, h01, l01);
            split2(v.z, v.w, h23, l23);
            uint32_t* ph = (uint32_t*)&smh[FXH + r * FKST + c4];
            uint32_t* pl = (uint32_t*)&smh[FXL + r * FKST + c4];
            ph[0] = h01; ph[1] = h23;
            pl[0] = l01; pl[1] = l23;
        }
        CPA_WAIT0();
        __syncthreads();

        #pragma unroll
        for (int s = 0; s < 4; s++) {
            const int kk = s * 16;
            uint32_t ah[2][4], al[2][4];
            #pragma unroll
            for (int mf = 0; mf < 2; mf++) {
                const int mr = mw * 32 + mf * 16 + g;
                const __nv_bfloat16* ph = &smh[FXH + mr * FKST + kk + 2 * t];
                const __nv_bfloat16* pl = &smh[FXL + mr * FKST + kk + 2 * t];
                ah[mf][0] = *(const uint32_t*)ph;
                ah[mf][1] = *(const uint32_t*)(ph + 8 * FKST);
                ah[mf][2] = *(const uint32_t*)(ph + 8);
                ah[mf][3] = *(const uint32_t*)(ph + 8 * FKST + 8);
                al[mf][0] = *(const uint32_t*)pl;
                al[mf][1] = *(const uint32_t*)(pl + 8 * FKST);
                al[mf][2] = *(const uint32_t*)(pl + 8);
                al[mf][3] = *(const uint32_t*)(pl + 8 * FKST + 8);
            }
            #pragma unroll
            for (int nf = 0; nf < 6; nf++) {
                const int nr = nw * 48 + nf * 8 + g;
                const __nv_bfloat16* ph = &smh[FWH + nr * FKST + kk + 2 * t];
                const __nv_bfloat16* pl = &smh[FWL + nr * FKST + kk + 2 * t];
                uint32_t bh[2], bl[2];
                bh[0] = *(const uint32_t*)ph;
                bh[1] = *(const uint32_t*)(ph + 8);
                bl[0] = *(const uint32_t*)pl;
                bl[1] = *(const uint32_t*)(pl + 8);
                mma16(c[0][nf], ah[0], bh);
                mma16(c[1][nf], ah[1], bh);
                mma16(c[0][nf], al[0], bh);
                mma16(c[1][nf], al[1], bh);
                mma16(c[0][nf], ah[0], bl);
                mma16(c[1][nf], ah[1], bl);
            }
        }
    }

    const int tile = m0 >> 6;
    #pragma unroll
    for (int mf = 0; mf < 2; mf++) {
        const int r0 = m0 + mw * 32 + mf * 16 + g;
        #pragma unroll
        for (int nf = 0; nf < 6; nf++) {
            const int ncol = nw * 48 + nf * 8;
            const int z    = ncol >> 6;
            const int d0   = (ncol & 63) + 2 * t;
            if (z == 0) {
                *(float2*)&g_q[(size_t)r0 * HD + d0] =
                    make_float2(c[mf][nf][0], c[mf][nf][1]);
                *(float2*)&g_q[(size_t)(r0 + 8) * HD + d0] =
                    make_float2(c[mf][nf][2], c[mf][nf][3]);
            } else if (z == 2) {
                *(float2*)&g_v[(size_t)r0 * HD + d0] =
                    make_float2(tf32f(c[mf][nf][0]), tf32f(c[mf][nf][1]));
                *(float2*)&g_v[(size_t)(r0 + 8) * HD + d0] =
                    make_float2(tf32f(c[mf][nf][2]), tf32f(c[mf][nf][3]));
            } else {
                const int d8 = (ncol & 63) >> 3;
                #pragma unroll
                for (int hi = 0; hi < 2; hi++) {
                    const int key = r0 + hi * 8;
                    const int n8  = (key >> 3) & 7;
                    float* tb = g_kF + (size_t)tile * 4096
                              + (d8 * 8 + n8) * 64 + g * 8;
                    #pragma unroll
                    for (int jj = 0; jj < 2; jj++) {
                        const int dm = 2 * t + jj;
                        tb[(dm & 3) * 2 + (dm >> 2)] =
                            tf32f(c[mf][nf][hi * 2 + jj]);
                    }
                }
            }
        }
    }
}

// -------------------------------------------------------------------------
// Flash attention (tf32 mma throughout, as R13) with double-buffered K/V:
// prefetch of tile tt+2 issued right after the arrival barrier, hiding the
// full L2 latency behind the S/exp/PV compute body. BQ=128, 8 warps 4m x 2n,
// split-K across blockIdx.z tile parity.
// -------------------------------------------------------------------------
#define NCHUNK2 (TSEQ / 128)   // 32
#define VP 72
#define PP 68
// smem float offsets
#define SK0 0
#define SK1 4096
#define SV0 8192
#define SV1 (SV0 + 64 * VP)                // 12800
#define SPP (SV1 + 64 * VP)                // 17408
#define SLS (SPP + 128 * PP)               // 26112
#define ATTN_SMEM ((SLS + 256) * 4)        // 105,472 B

__global__ __launch_bounds__(256) void attn_kernel()
{
    constexpr float SCALE = 0.03125f;
    constexpr float SLOPE = 0.70710678118654752f;

    extern __shared__ float sm[];
    const int b    = blockIdx.y;
    const int sz   = blockIdx.z;           // tile parity 0/1
    const size_t bT = (size_t)b * TSEQ;
    const int tid  = threadIdx.x;
    const int lane = tid & 31;
    const int wid  = tid >> 5;
    const int mw   = wid >> 1;   // 0..3 : 32-row slice
    const int nw   = wid & 1;    // 0..1 : 32-key slice
    const int g    = lane >> 2;
    const int t    = lane & 3;

    float* oP = g_oP + (size_t)sz * MTOT * HD;
    float* lP = g_lP + (size_t)sz * MTOT;

    // staging index precomputes
    const int rr  = tid >> 4;        // 0..15
    const int lc4 = (tid & 15) * 4;  // 0..60

    #pragma unroll 1
    for (int half = 0; half < 2; half++) {
        const int chunk = half ? (NCHUNK2 - 1 - (int)blockIdx.x) : (int)blockIdx.x;
        const int q0 = chunk * 128;
        const int nT = 2 * chunk + 2;

        __syncthreads();   // previous chunk fully done with smem

        // ---- prologue: stage first tile (parity sz) into buffer 0 ----
        {
            const int j0 = sz * 64;
            const float* ks = g_kF + (bT + j0) * 64;
            #pragma unroll
            for (int it = 0; it < 4; it++) {
                int f4 = it * 256 + tid;
                uint32_t d = (uint32_t)__cvta_generic_to_shared(sm + SK0 + f4 * 4);
                CPA16(d, ks + f4 * 4);
            }
            #pragma unroll
            for (int it = 0; it < 4; it++) {
                const int r = rr + it * 16;
                uint32_t d = (uint32_t)__cvta_generic_to_shared(sm + SV0 + r * VP + lc4);
                CPA16(d, g_v + (bT + j0 + r) * HD + lc4);
            }
            CPA_COMMIT();
        }

        // ---- Q A-fragments, register resident per chunk ----
        uint32_t qa[2][8][4];
        #pragma unroll
        for (int mf = 0; mf < 2; mf++) {
            const float* qp  = g_q + (bT + q0 + mw * 32 + mf * 16 + g) * HD;
            const float* qp8 = qp + 8 * HD;
            #pragma unroll
            for (int tk = 0; tk < 8; tk++) {
                qa[mf][tk][0] = f2tf(qp [tk * 8 + t]     * SCALE);
                qa[mf][tk][1] = f2tf(qp8[tk * 8 + t]     * SCALE);
                qa[mf][tk][2] = f2tf(qp [tk * 8 + t + 4] * SCALE);
                qa[mf][tk][3] = f2tf(qp8[tk * 8 + t + 4] * SCALE);
            }
        }

        float of[2][4][4] = {};
        float rs[2][2] = {};

        #pragma unroll 1
        for (int tt = sz; tt < nT; tt += 2) {
            const int j0  = tt * 64;
            const int buf = (tt >> 1) & 1;
            const float* Kc = sm + (buf ? SK1 : SK0);
            const float* Vc = sm + (buf ? SV1 : SV0);

            CPA_WAIT0();       // tile tt arrived
            __syncthreads();   // all warps past previous PV; alt buffers free

            // ---- prefetch tile tt+2 into the alternate buffer ----
            if (tt + 2 < nT) {
                float* Kn = sm + (buf ? SK0 : SK1);
                float* Vn = sm + (buf ? SV0 : SV1);
                const float* ks = g_kF + (bT + j0 + 128) * 64;
                #pragma unroll
                for (int it = 0; it < 4; it++) {
                    int f4 = it * 256 + tid;
                    uint32_t d = (uint32_t)__cvta_generic_to_shared(Kn + f4 * 4);
                    CPA16(d, ks + f4 * 4);
                }
                #pragma unroll
                for (int it = 0; it < 4; it++) {
                    const int r = rr + it * 16;
                    uint32_t d = (uint32_t)__cvta_generic_to_shared(Vn + r * VP + lc4);
                    CPA16(d, g_v + (bT + j0 + 128 + r) * HD + lc4);
                }
                CPA_COMMIT();
            }

            // ---- S = Q K^T ----
            float sc[2][4][4] = {};
            #pragma unroll
            for (int tk = 0; tk < 8; tk++) {
                #pragma unroll
                for (int ns = 0; ns < 4; ns++) {
                    float2 kb = *(const float2*)
                        &Kc[((tk * 8 + nw * 4 + ns) * 32 + lane) * 2];
                    const uint32_t b0 = __float_as_uint(kb.x);
                    const uint32_t b1 = __float_as_uint(kb.y);
                    mma8(sc[0][ns], qa[0][tk], b0, b1);
                    mma8(sc[1][ns], qa[1][tk], b0, b1);
                }
            }

            // ---- ALiBi + causal + exp, stage P ----
            const bool diag = (j0 >= q0);
            #pragma unroll
            for (int mf = 0; mf < 2; mf++) {
                const int qrLo = q0 + mw * 32 + mf * 16 + g;
                const int qrHi = qrLo + 8;
                #pragma unroll
                for (int ns = 0; ns < 4; ns++) {
                    const int k0c = j0 + nw * 32 + ns * 8 + 2 * t;
                    float p0 = __expf(sc[mf][ns][0] + SLOPE * (float)(k0c     - qrLo));
                    float p1 = __expf(sc[mf][ns][1] + SLOPE * (float)(k0c + 1 - qrLo));
                    float p2 = __expf(sc[mf][ns][2] + SLOPE * (float)(k0c     - qrHi));
                    float p3 = __expf(sc[mf][ns][3] + SLOPE * (float)(k0c + 1 - qrHi));
                    if (diag) {
                        if (k0c     > qrLo) p0 = 0.0f;
                        if (k0c + 1 > qrLo) p1 = 0.0f;
                        if (k0c     > qrHi) p2 = 0.0f;
                        if (k0c + 1 > qrHi) p3 = 0.0f;
                    }
                    rs[mf][0] += p0 + p1;
                    rs[mf][1] += p2 + p3;
                    float* Pr = sm + SPP + (mw * 32 + mf * 16 + g) * PP
                              + nw * 32 + ns * 8 + 2 * t;
                    *(float2*)Pr            = make_float2(tf32f(p0), tf32f(p1));
                    *(float2*)(Pr + 8 * PP) = make_float2(tf32f(p2), tf32f(p3));
                }
            }
            __syncthreads();   // P visible

            // ---- O += P V ----
            #pragma unroll
            for (int pk = 0; pk < 8; pk++) {
                uint32_t pa[2][4];
                #pragma unroll
                for (int mf = 0; mf < 2; mf++) {
                    const float* Pb = sm + SPP + (mw * 32 + mf * 16 + g) * PP
                                    + pk * 8 + t;
                    pa[mf][0] = __float_as_uint(Pb[0]);
                    pa[mf][1] = __float_as_uint(Pb[8 * PP]);
                    pa[mf][2] = __float_as_uint(Pb[4]);
                    pa[mf][3] = __float_as_uint(Pb[8 * PP + 4]);
                }
                const float* Vb = Vc + (pk * 8 + t) * VP + nw * 32 + g;
                #pragma unroll
                for (int ns = 0; ns < 4; ns++) {
                    uint32_t vb0 = __float_as_uint(Vb[ns * 8]);
                    uint32_t vb1 = __float_as_uint(Vb[ns * 8 + 4 * VP]);
                    mma8(of[0][ns], pa[0], vb0, vb1);
                    mma8(of[1][ns], pa[1], vb0, vb1);
                }
            }
        }

        // ---- epilogue: partial row sums + unnormalized O to scratch ----
        __syncthreads();   // all PV reads done before P/L smem reuse
        #pragma unroll
        for (int mf = 0; mf < 2; mf++)
            #pragma unroll
            for (int hv = 0; hv < 2; hv++) {
                float l = rs[mf][hv];
                l += __shfl_xor_sync(0xffffffffu, l, 1);
                l += __shfl_xor_sync(0xffffffffu, l, 2);
                if (t == 0)
                    sm[SLS + nw * 128 + mw * 32 + mf * 16 + hv * 8 + g] = l;
            }
        __syncthreads();
        if (nw == 0 && t == 0) {
            #pragma unroll
            for (int mf = 0; mf < 2; mf++)
                #pragma unroll
                for (int hv = 0; hv < 2; hv++) {
                    const int row = mw * 32 + mf * 16 + hv * 8 + g;
                    lP[bT + q0 + row] = sm[SLS + row] + sm[SLS + 128 + row];
                }
        }
        #pragma unroll
        for (int mf = 0; mf < 2; mf++) {
            const int row = mw * 32 + mf * 16 + g;
            #pragma unroll
            for (int ns = 0; ns < 4; ns++) {
                float* orow = oP + (bT + q0 + row) * HD + nw * 32 + ns * 8 + 2 * t;
                *(float2*)orow            = make_float2(of[mf][ns][0], of[mf][ns][1]);
                *(float2*)(orow + 8 * HD) = make_float2(of[mf][ns][2], of[mf][ns][3]);
            }
        }
    }
}

// -------------------------------------------------------------------------
// Combine split-K partials: out = (O0 + O1) / (l0 + l1)
// -------------------------------------------------------------------------
__global__ __launch_bounds__(256) void combine_kernel(float* __restrict__ out)
{
    const int idx = blockIdx.x * 256 + threadIdx.x;
    const int row = idx >> 4;
    float4 a = ((const float4*)g_oP)[idx];
    float4 c = ((const float4*)(g_oP + (size_t)MTOT * HD))[idx];
    const float inv = 1.0f / (g_lP[row] + g_lP[MTOT + row]);
    float4 r;
    r.x = (a.x + c.x) * inv;
    r.y = (a.y + c.y) * inv;
    r.z = (a.z + c.z) * inv;
    r.w = (a.w + c.w) * inv;
    ((float4*)out)[idx] = r;
}

// -------------------------------------------------------------------------
extern "C" void kernel_launch(void* const* d_in, const int* in_sizes, int n_in,
                              void* d_out, int out_size)
{
    const float* x  = (const float*)d_in[0];
    const float* wq = (const float*)d_in[1];
    const float* wk = (const float*)d_in[2];
    const float* wv = (const float*)d_in[3];
    float* out = (float*)d_out;

    (void)in_sizes; (void)n_in; (void)out_size;

    cudaFuncSetAttribute(qkv_fused,
                         cudaFuncAttributeMaxDynamicSharedMemorySize, FUSED_SMEM);
    cudaFuncSetAttribute(attn_kernel,
                         cudaFuncAttributeMaxDynamicSharedMemorySize, ATTN_SMEM);

    wprep_kernel<<<192, 256>>>(wq, wk, wv);               // 196K elems

    qkv_fused<<<MTOT / 64, 256, FUSED_SMEM>>>(x);         // 256 blocks

    dim3 agrid(NCHUNK2 / 2, BATCH, 2);                    // 16 x 4 x 2 = 128
    attn_kernel<<<agrid, 256, ATTN_SMEM>>>();

    combine_kernel<<<MTOT * HD / 1024, 256>>>(out);       // 1024 blocks
}

// round 17
// speedup vs baseline: 1.4167x; 1.4167x over previous
#include <cuda_runtime.h>
#include <cuda_bf16.h>
#include <cstdint>

// Problem constants
#define BATCH 4
#define TSEQ  4096
#define CEMB  1024
#define HD    64
#define MTOT  (BATCH * TSEQ)          // 16384 tokens

__device__ float g_q [MTOT * HD];     // [token][d] row-major (fp32)
__device__ float g_kF[MTOT * HD];     // B-fragment-major per 64-key tile (tf32 bits)
__device__ float g_v [MTOT * HD];     // [token][d] row-major (tf32-rounded)
__device__ float g_oP[2 * MTOT * HD]; // split-K partial O (unnormalized)
__device__ float g_lP[2 * MTOT];      // split-K partial row sums
__device__ __nv_bfloat16 g_wh[3 * HD * CEMB];  // [z*64+h][c] hi
__device__ __nv_bfloat16 g_wl[3 * HD * CEMB];  // [z*64+h][c] lo

// ---- tf32 / mma helpers --------------------------------------------------
__device__ __forceinline__ uint32_t f2tf(float f) {
    uint32_t u;
    asm("cvt.rna.tf32.f32 %0, %1;" : "=r"(u) : "f"(f));
    return u;
}
__device__ __forceinline__ float tf32f(float f) { return __uint_as_float(f2tf(f)); }

__device__ __forceinline__ void mma8(float c[4], const uint32_t a[4],
                                     uint32_t b0, uint32_t b1) {
    asm volatile(
        "mma.sync.aligned.m16n8k8.row.col.f32.tf32.tf32.f32 "
        "{%0,%1,%2,%3}, {%4,%5,%6,%7}, {%8,%9}, {%0,%1,%2,%3};"
        : "+f"(c[0]), "+f"(c[1]), "+f"(c[2]), "+f"(c[3])
        : "r"(a[0]), "r"(a[1]), "r"(a[2]), "r"(a[3]), "r"(b0), "r"(b1));
}

__device__ __forceinline__ void mma16(float c[4], const uint32_t a[4],
                                      const uint32_t b[2]) {
    asm volatile(
        "mma.sync.aligned.m16n8k16.row.col.f32.bf16.bf16.f32 "
        "{%0,%1,%2,%3}, {%4,%5,%6,%7}, {%8,%9}, {%0,%1,%2,%3};"
        : "+f"(c[0]), "+f"(c[1]), "+f"(c[2]), "+f"(c[3])
        : "r"(a[0]), "r"(a[1]), "r"(a[2]), "r"(a[3]), "r"(b[0]), "r"(b[1]));
}

#define CPA16(dst_s32, src) \
    asm volatile("cp.async.ca.shared.global [%0], [%1], 16;" :: "r"(dst_s32), "l"(src))
#define CPA_COMMIT() asm volatile("cp.async.commit_group;")
#define CPA_WAIT0()  asm volatile("cp.async.wait_group 0;" ::: "memory")

__device__ __forceinline__ uint32_t packbf(__nv_bfloat16 a, __nv_bfloat16 b) {
    __nv_bfloat162 v(a, b);
    return *reinterpret_cast<uint32_t*>(&v);
}
__device__ __forceinline__ void split2(float f0, float f1,
                                       uint32_t& h, uint32_t& l) {
    __nv_bfloat16 h0 = __float2bfloat16(f0);
    __nv_bfloat16 h1 = __float2bfloat16(f1);
    __nv_bfloat16 l0 = __float2bfloat16(f0 - __bfloat162float(h0));
    __nv_bfloat16 l1 = __float2bfloat16(f1 - __bfloat162float(h1));
    h = packbf(h0, h1);
    l = packbf(l0, l1);
}

// -------------------------------------------------------------------------
// Weight split prep: w (fp32 [h][c], 3 tensors) -> g_wh/g_wl bf16 [z*64+h][c]
// -------------------------------------------------------------------------
__global__ __launch_bounds__(256) void wprep_kernel(
    const float* __restrict__ wq,
    const float* __restrict__ wk,
    const float* __restrict__ wv)
{
    const int idx  = blockIdx.x * 256 + threadIdx.x;
    const int base = idx * 4;
    const int row  = base >> 10;
    const int c    = base & 1023;
    const int z    = row >> 6;
    const int h    = row & 63;
    const float* w = (z == 0) ? wq : (z == 1) ? wk : wv;
    float4 v = *(const float4*)&w[(size_t)h * CEMB + c];
    uint32_t h01, l01, h23, l23;
    split2(v.x, v.y, h01, l01);
    split2(v.z, v.w, h23, l23);
    uint32_t* ph = (uint32_t*)&g_wh[base];
    uint32_t* pl = (uint32_t*)&g_wl[base];
    ph[0] = h01; ph[1] = h23;
    pl[0] = l01; pl[1] = l23;
}

// -------------------------------------------------------------------------
// Fused QKV projection on tensor cores (identical to R13).
// -------------------------------------------------------------------------
#define FKST 72   // smem k-stride (bf16 elems)
#define FXH 0
#define FXL (64 * FKST)
#define FWH (2 * 64 * FKST)
#define FWL (FWH + 192 * FKST)
#define FUSED_SMEM_HALFS (FWL + 192 * FKST)
#define FUSED_SMEM ((int)(FUSED_SMEM_HALFS * sizeof(__nv_bfloat16)))  // 73,728 B

__global__ __launch_bounds__(256, 2) void qkv_fused(const float* __restrict__ x)
{
    extern __shared__ __nv_bfloat16 smh[];

    const int m0   = blockIdx.x * 64;
    const int tid  = threadIdx.x;
    const int lane = tid & 31;
    const int wid  = tid >> 5;
    const int mw   = wid >> 2;    // 0..1
    const int nw   = wid & 3;     // 0..3
    const int g    = lane >> 2;
    const int t    = lane & 3;

    float c[2][6][4] = {};

    for (int k0 = 0; k0 < CEMB; k0 += 64) {
        __syncthreads();

        #pragma unroll
        for (int it = 0; it < 6; it++) {
            int ch  = tid + it * 256;
            int r   = ch >> 3;
            int c8  = (ch & 7) * 8;
            uint32_t dh = (uint32_t)__cvta_generic_to_shared(
                &smh[FWH + r * FKST + c8]);
            uint32_t dl = (uint32_t)__cvta_generic_to_shared(
                &smh[FWL + r * FKST + c8]);
            CPA16(dh, &g_wh[(size_t)r * CEMB + k0 + c8]);
            CPA16(dl, &g_wl[(size_t)r * CEMB + k0 + c8]);
        }
        CPA_COMMIT();

        #pragma unroll
        for (int it = 0; it < 4; it++) {
            int f  = tid + it * 256;
            int r  = f >> 4;
            int c4 = (f & 15) * 4;
            float4 v = *(const float4*)&x[(size_t)(m0 + r) * CEMB + k0 + c4];
            uint32_t h01, l01, h23, l23;
            split2(v.x, v.y, h01, l01);
            split2(v.z, v.w, h23, l23);
            uint32_t* ph = (uint32_t*)&smh[FXH + r * FKST + c4];
            uint32_t* pl = (uint32_t*)&smh[FXL + r * FKST + c4];
            ph[0] = h01; ph[1] = h23;
            pl[0] = l01; pl[1] = l23;
        }
        CPA_WAIT0();
        __syncthreads();

        #pragma unroll
        for (int s = 0; s < 4; s++) {
            const int kk = s * 16;
            uint32_t ah[2][4], al[2][4];
            #pragma unroll
            for (int mf = 0; mf < 2; mf++) {
                const int mr = mw * 32 + mf * 16 + g;
                const __nv_bfloat16* ph = &smh[FXH + mr * FKST + kk + 2 * t];
                const __nv_bfloat16* pl = &smh[FXL + mr * FKST + kk + 2 * t];
                ah[mf][0] = *(const uint32_t*)ph;
                ah[mf][1] = *(const uint32_t*)(ph + 8 * FKST);
                ah[mf][2] = *(const uint32_t*)(ph + 8);
                ah[mf][3] = *(const uint32_t*)(ph + 8 * FKST + 8);
                al[mf][0] = *(const uint32_t*)pl;
                al[mf][1] = *(const uint32_t*)(pl + 8 * FKST);
                al[mf][2] = *(const uint32_t*)(pl + 8);
                al[mf][3] = *(const uint32_t*)(pl + 8 * FKST + 8);
            }
            #pragma unroll
            for (int nf = 0; nf < 6; nf++) {
                const int nr = nw * 48 + nf * 8 + g;
                const __nv_bfloat16* ph = &smh[FWH + nr * FKST + kk + 2 * t];
                const __nv_bfloat16* pl = &smh[FWL + nr * FKST + kk + 2 * t];
                uint32_t bh[2], bl[2];
                bh[0] = *(const uint32_t*)ph;
                bh[1] = *(const uint32_t*)(ph + 8);
                bl[0] = *(const uint32_t*)pl;
                bl[1] = *(const uint32_t*)(pl + 8);
                mma16(c[0][nf], ah[0], bh);
                mma16(c[1][nf], ah[1], bh);
                mma16(c[0][nf], al[0], bh);
                mma16(c[1][nf], al[1], bh);
                mma16(c[0][nf], ah[0], bl);
                mma16(c[1][nf], ah[1], bl);
            }
        }
    }

    const int tile = m0 >> 6;
    #pragma unroll
    for (int mf = 0; mf < 2; mf++) {
        const int r0 = m0 + mw * 32 + mf * 16 + g;
        #pragma unroll
        for (int nf = 0; nf < 6; nf++) {
            const int ncol = nw * 48 + nf * 8;
            const int z    = ncol >> 6;
            const int d0   = (ncol & 63) + 2 * t;
            if (z == 0) {
                *(float2*)&g_q[(size_t)r0 * HD + d0] =
                    make_float2(c[mf][nf][0], c[mf][nf][1]);
                *(float2*)&g_q[(size_t)(r0 + 8) * HD + d0] =
                    make_float2(c[mf][nf][2], c[mf][nf][3]);
            } else if (z == 2) {
                *(float2*)&g_v[(size_t)r0 * HD + d0] =
                    make_float2(tf32f(c[mf][nf][0]), tf32f(c[mf][nf][1]));
                *(float2*)&g_v[(size_t)(r0 + 8) * HD + d0] =
                    make_float2(tf32f(c[mf][nf][2]), tf32f(c[mf][nf][3]));
            } else {
                const int d8 = (ncol & 63) >> 3;
                #pragma unroll
                for (int hi = 0; hi < 2; hi++) {
                    const int key = r0 + hi * 8;
                    const int n8  = (key >> 3) & 7;
                    float* tb = g_kF + (size_t)tile * 4096
                              + (d8 * 8 + n8) * 64 + g * 8;
                    #pragma unroll
                    for (int jj = 0; jj < 2; jj++) {
                        const int dm = 2 * t + jj;
                        tb[(dm & 3) * 2 + (dm >> 2)] =
                            tf32f(c[mf][nf][hi * 2 + jj]);
                    }
                }
            }
        }
    }
}

// -------------------------------------------------------------------------
// Flash attention (tf32 mma, R13 math) with 512 threads = 16 warps arranged
// 8(m) x 2(n): warp tile 16 rows x 32 keys. Same smem layout and byte
// traffic as R13, but 2x the warps driving the crossbar. Split-K across
// blockIdx.z tile parity; unnormalized partials to scratch.
// -------------------------------------------------------------------------
#define NCHUNK2 (TSEQ / 128)   // 32
#define VP 72
#define PP 68
#define SK  0
#define SV  4096
#define SPP (SV + 64 * VP)                 // 8704
#define SLS (SPP + 128 * PP)               // 17408
#define ATTN_SMEM ((SLS + 256) * 4)        // 70,656 B

__global__ __launch_bounds__(512) void attn_kernel()
{
    constexpr float SCALE = 0.03125f;
    constexpr float SLOPE = 0.70710678118654752f;

    extern __shared__ float sm[];
    const int b    = blockIdx.y;
    const int sz   = blockIdx.z;           // tile parity 0/1
    const size_t bT = (size_t)b * TSEQ;
    const int tid  = threadIdx.x;
    const int lane = tid & 31;
    const int wid  = tid >> 5;
    const int mw   = wid >> 1;   // 0..7 : 16-row slice
    const int nw   = wid & 1;    // 0..1 : 32-key / 32-d slice
    const int g    = lane >> 2;
    const int t    = lane & 3;

    float* oP = g_oP + (size_t)sz * MTOT * HD;
    float* lP = g_lP + (size_t)sz * MTOT;

    #pragma unroll 1
    for (int half = 0; half < 2; half++) {
        const int chunk = half ? (NCHUNK2 - 1 - (int)blockIdx.x) : (int)blockIdx.x;
        const int q0 = chunk * 128;
        const int nT = 2 * chunk + 2;

        __syncthreads();   // previous chunk fully done with smem

        // ---- Q A-fragments (one m16 frag per warp), register resident ----
        uint32_t qa[8][4];
        {
            const float* qp  = g_q + (bT + q0 + mw * 16 + g) * HD;
            const float* qp8 = qp + 8 * HD;
            #pragma unroll
            for (int tk = 0; tk < 8; tk++) {
                qa[tk][0] = f2tf(qp [tk * 8 + t]     * SCALE);
                qa[tk][1] = f2tf(qp8[tk * 8 + t]     * SCALE);
                qa[tk][2] = f2tf(qp [tk * 8 + t + 4] * SCALE);
                qa[tk][3] = f2tf(qp8[tk * 8 + t + 4] * SCALE);
            }
        }

        float of[4][4] = {};
        float rs[2] = {};

        #pragma unroll 1
        for (int tt = sz; tt < nT; tt += 2) {
            const int j0 = tt * 64;

            // ---- stage K/V tile (512 threads: 2 iters each) ----
            {
                const float* ks = g_kF + (bT + j0) * 64;
                #pragma unroll
                for (int it = 0; it < 2; it++) {
                    int f4 = it * 512 + tid;
                    uint32_t d = (uint32_t)__cvta_generic_to_shared(sm + SK + f4 * 4);
                    CPA16(d, ks + f4 * 4);
                }
                #pragma unroll
                for (int it = 0; it < 2; it++) {
                    int f = it * 512 + tid;
                    int r = f >> 4, c4 = (f & 15) * 4;
                    uint32_t d = (uint32_t)__cvta_generic_to_shared(sm + SV + r * VP + c4);
                    CPA16(d, g_v + (bT + j0 + r) * HD + c4);
                }
                CPA_COMMIT();
            }
            CPA_WAIT0();
            __syncthreads();   // tile staged

            // ---- S = Q K^T ----
            float sc[4][4] = {};
            #pragma unroll
            for (int tk = 0; tk < 8; tk++) {
                #pragma unroll
                for (int ns = 0; ns < 4; ns++) {
                    float2 kb = *(const float2*)
                        &sm[SK + ((tk * 8 + nw * 4 + ns) * 32 + lane) * 2];
                    mma8(sc[ns], qa[tk],
                         __float_as_uint(kb.x), __float_as_uint(kb.y));
                }
            }

            // ---- ALiBi + causal + exp, stage P ----
            const bool diag = (j0 >= q0);
            const int qrLo = q0 + mw * 16 + g;
            const int qrHi = qrLo + 8;
            #pragma unroll
            for (int ns = 0; ns < 4; ns++) {
                const int k0c = j0 + nw * 32 + ns * 8 + 2 * t;
                float p0 = __expf(sc[ns][0] + SLOPE * (float)(k0c     - qrLo));
                float p1 = __expf(sc[ns][1] + SLOPE * (float)(k0c + 1 - qrLo));
                float p2 = __expf(sc[ns][2] + SLOPE * (float)(k0c     - qrHi));
                float p3 = __expf(sc[ns][3] + SLOPE * (float)(k0c + 1 - qrHi));
                if (diag) {
                    if (k0c     > qrLo) p0 = 0.0f;
                    if (k0c + 1 > qrLo) p1 = 0.0f;
                    if (k0c     > qrHi) p2 = 0.0f;
                    if (k0c + 1 > qrHi) p3 = 0.0f;
                }
                rs[0] += p0 + p1;
                rs[1] += p2 + p3;
                float* Pr = sm + SPP + (mw * 16 + g) * PP + nw * 32 + ns * 8 + 2 * t;
                *(float2*)Pr            = make_float2(tf32f(p0), tf32f(p1));
                *(float2*)(Pr + 8 * PP) = make_float2(tf32f(p2), tf32f(p3));
            }
            __syncthreads();   // P visible

            // ---- O += P V ----
            #pragma unroll
            for (int pk = 0; pk < 8; pk++) {
                uint32_t pa[4];
                const float* Pb = sm + SPP + (mw * 16 + g) * PP + pk * 8 + t;
                pa[0] = __float_as_uint(Pb[0]);
                pa[1] = __float_as_uint(Pb[8 * PP]);
                pa[2] = __float_as_uint(Pb[4]);
                pa[3] = __float_as_uint(Pb[8 * PP + 4]);
                const float* Vb = sm + SV + (pk * 8 + t) * VP + nw * 32 + g;
                #pragma unroll
                for (int ns = 0; ns < 4; ns++) {
                    uint32_t vb0 = __float_as_uint(Vb[ns * 8]);
                    uint32_t vb1 = __float_as_uint(Vb[ns * 8 + 4 * VP]);
                    mma8(of[ns], pa, vb0, vb1);
                }
            }
            __syncthreads();   // PV done; K/V/P free for next tile
        }

        // ---- epilogue: partial row sums + unnormalized O to scratch ----
        #pragma unroll
        for (int hv = 0; hv < 2; hv++) {
            float l = rs[hv];
            l += __shfl_xor_sync(0xffffffffu, l, 1);
            l += __shfl_xor_sync(0xffffffffu, l, 2);
            if (t == 0)
                sm[SLS + nw * 128 + mw * 16 + hv * 8 + g] = l;
        }
        __syncthreads();
        if (nw == 0 && t == 0) {
            #pragma unroll
            for (int hv = 0; hv < 2; hv++) {
                const int row = mw * 16 + hv * 8 + g;
                lP[bT + q0 + row] = sm[SLS + row] + sm[SLS + 128 + row];
            }
        }
        {
            const int row = mw * 16 + g;
            #pragma unroll
            for (int ns = 0; ns < 4; ns++) {
                float* orow = oP + (bT + q0 + row) * HD + nw * 32 + ns * 8 + 2 * t;
                *(float2*)orow            = make_float2(of[ns][0], of[ns][1]);
                *(float2*)(orow + 8 * HD) = make_float2(of[ns][2], of[ns][3]);
            }
        }
    }
}

// -------------------------------------------------------------------------
// Combine split-K partials: out = (O0 + O1) / (l0 + l1)
// -------------------------------------------------------------------------
__global__ __launch_bounds__(256) void combine_kernel(float* __restrict__ out)
{
    const int idx = blockIdx.x * 256 + threadIdx.x;
    const int row = idx >> 4;
    float4 a = ((const float4*)g_oP)[idx];
    float4 c = ((const float4*)(g_oP + (size_t)MTOT * HD))[idx];
    const float inv = 1.0f / (g_lP[row] + g_lP[MTOT + row]);
    float4 r;
    r.x = (a.x + c.x) * inv;
    r.y = (a.y + c.y) * inv;
    r.z = (a.z + c.z) * inv;
    r.w = (a.w + c.w) * inv;
    ((float4*)out)[idx] = r;
}

// -------------------------------------------------------------------------
extern "C" void kernel_launch(void* const* d_in, const int* in_sizes, int n_in,
                              void* d_out, int out_size)
{
    const float* x  = (const float*)d_in[0];
    const float* wq = (const float*)d_in[1];
    const float* wk = (const float*)d_in[2];
    const float* wv = (const float*)d_in[3];
    float* out = (float*)d_out;

    (void)in_sizes; (void)n_in; (void)out_size;

    cudaFuncSetAttribute(qkv_fused,
                         cudaFuncAttributeMaxDynamicSharedMemorySize, FUSED_SMEM);
    cudaFuncSetAttribute(attn_kernel,
                         cudaFuncAttributeMaxDynamicSharedMemorySize, ATTN_SMEM);

    wprep_kernel<<<192, 256>>>(wq, wk, wv);               // 196K elems

    qkv_fused<<<MTOT / 64, 256, FUSED_SMEM>>>(x);         // 256 blocks

    dim3 agrid(NCHUNK2 / 2, BATCH, 2);                    // 16 x 4 x 2 = 128
    attn_kernel<<<agrid, 512, ATTN_SMEM>>>();

    combine_kernel<<<MTOT * HD / 1024, 256>>>(out);       // 1024 blocks
}